// round 9
// baseline (speedup 1.0000x reference)
#include <cuda_runtime.h>
#include <cuda_bf16.h>
#include <cstdint>

#define NB   1024
#define CD   512
#define NN   32
#define TD   2048
#define NT   (NN*TD)      // 65536 rows
#define MT   128          // rows per CTA
#define NTILE (NT/MT)     // 512 CTAs
#define NTHR 512
#define PASSES 8
#define PN   128          // codes per pass
#define KC   128          // k per chunk
#define NCH  4            // chunks per pass
#define CHT  (PASSES*NCH) // 32 chunks total
#define MARGIN 1.5f
#define CMAX 8

typedef unsigned long long ull;

__device__ __align__(16) __nv_bfloat16 g_cb16[NB*CD];
__device__ float g_cbnorm[NB];
__device__ int   g_counts[NB];
__device__ float g_partials[NTILE];
__device__ unsigned int g_done;

// smem map (bytes): A 128x512 bf16 swizzled @0 (131072; later qt staging / finalize scratch),
// B 2x32768 @131072 (later cand 64KB), cbn @196608 (4096), sidx @200704 (512), wred @201216
#define SA    0
#define SB    131072
#define SCBN  196608
#define SIDX  200704
#define SWRED 201216
#define SFLAG 201280
#define SMTOT 201344

static __device__ __forceinline__ uint32_t smem_u32(const void* p){
    uint32_t a; asm("{ .reg .u64 t; cvta.to.shared.u64 t, %1; cvt.u32.u64 %0, t; }" : "=r"(a) : "l"(p));
    return a;
}
static __device__ __forceinline__ uint32_t A_off(int r, int c){
    int ck = c >> 3;
    int cks = (ck & ~7) | ((ck ^ r) & 7);
    return (uint32_t)(r*1024 + cks*16 + (c&7)*2);
}
static __device__ __forceinline__ uint32_t B_off(int j, int kk){
    int ck = kk >> 3;
    int cks = (ck & 8) | ((ck ^ j) & 7);
    return (uint32_t)(j*256 + cks*16 + (kk&7)*2);
}
static __device__ __forceinline__ void ldsm4(uint32_t* r, uint32_t addr){
    asm volatile("ldmatrix.sync.aligned.m8n8.x4.shared.b16 {%0,%1,%2,%3}, [%4];"
        : "=r"(r[0]), "=r"(r[1]), "=r"(r[2]), "=r"(r[3]) : "r"(addr));
}
static __device__ __forceinline__ void mma16816(float* c, const uint32_t* a, uint32_t b0, uint32_t b1){
    asm volatile("mma.sync.aligned.m16n8k16.row.col.f32.bf16.bf16.f32 "
        "{%0,%1,%2,%3}, {%4,%5,%6,%7}, {%8,%9}, {%0,%1,%2,%3};"
        : "+f"(c[0]), "+f"(c[1]), "+f"(c[2]), "+f"(c[3])
        : "r"(a[0]), "r"(a[1]), "r"(a[2]), "r"(a[3]), "r"(b0), "r"(b1));
}

// ---------------- kernel 0: codebook norms + bf16 convert + zero counts/ticket ----------------
__global__ void k_norms(const float* __restrict__ cb){
    int j = blockIdx.x;
    float s = 0.f;
    for (int c = threadIdx.x; c < CD; c += 128){
        float v = cb[(size_t)j*CD + c];
        g_cb16[(size_t)j*CD + c] = __float2bfloat16(v);
        s = fmaf(v, v, s);
    }
    #pragma unroll
    for (int o = 16; o; o >>= 1) s += __shfl_xor_sync(~0u, s, o);
    __shared__ float ws[4];
    if ((threadIdx.x & 31) == 0) ws[threadIdx.x >> 5] = s;
    __syncthreads();
    if (threadIdx.x == 0){
        g_cbnorm[j] = (ws[0] + ws[1]) + (ws[2] + ws[3]);
        g_counts[j] = 0;
        if (j == 0) g_done = 0u;
    }
}

// ---------------- B chunk stage via cp.async (512 threads) ----------------
static __device__ __forceinline__ void issueB(int q, int tid, uint32_t sbase){
    int p = q >> 2, kc = q & 3;
    const __nv_bfloat16* src0 = g_cb16 + (size_t)p*PN*CD + kc*KC;
    uint32_t bufb = sbase + SB + (uint32_t)(q & 1)*32768u;
    #pragma unroll
    for (int it = 0; it < 4; ++it){
        int idx = tid + it*NTHR;              // 0..2047 16B units
        int j = idx >> 4, ck = idx & 15;
        uint32_t dst = bufb + (uint32_t)(j*256 + (((ck & 8) | ((ck ^ j) & 7)) << 4));
        const void* srcp = (const void*)(src0 + (size_t)j*CD + ck*8);
        asm volatile("cp.async.cg.shared.global [%0], [%1], 16;" :: "r"(dst), "l"(srcp));
    }
    asm volatile("cp.async.commit_group;");
}

// ---------------- kernel 1: fused GEMM + top2 + refine + output + commit + finalize ----------------
__global__ __launch_bounds__(NTHR, 1)
void k_main(const float* __restrict__ x, const float* __restrict__ cb, float* __restrict__ out){
    extern __shared__ char sm[];
    const uint32_t sbase = smem_u32(sm);
    const int tid = threadIdx.x;
    const int wid = tid >> 5, l = tid & 31;
    const int wm = wid >> 3, wn = wid & 7;        // 2 M-warps x 8 N-warps
    const int b = blockIdx.x, n = b >> 4, t0 = (b & 15) * MT;
    const float* xblk = x + (size_t)n*CD*TD + t0;
    float* outblk     = out + (size_t)n*CD*TD + t0;
    float* cbn_s = (float*)(sm + SCBN);
    int*   sidx  = (int*)(sm + SIDX);
    float* wred  = (float*)(sm + SWRED);
    int*   sflag = (int*)(sm + SFLAG);

    for (int i = tid; i < NB; i += NTHR) cbn_s[i] = g_cbnorm[i];

    // ---- stage A: x tile -> bf16, swizzled [t][c] ----
    #pragma unroll 4
    for (int it = 0; it < 64; ++it){
        int idx = tid + it*NTHR;
        int t = idx & 127, c = (idx >> 7) * 2;
        float v0 = xblk[(size_t)c*TD + t];
        float v1 = xblk[(size_t)(c+1)*TD + t];
        __nv_bfloat162 pk = __floats2bfloat162_rn(v0, v1);
        *(__nv_bfloat162*)(sm + SA + A_off(t, c)) = pk;
    }
    __syncthreads();

    issueB(0, tid, sbase);

    float bd[8][2]; int bj[8][2];
    #pragma unroll
    for (int r = 0; r < 8; ++r){
        bd[r][0] = bd[r][1] = 3.4e38f; bj[r][0] = bj[r][1] = 0;
    }

    const int arow = wm*64 + ((l >> 3) & 1)*8 + (l & 7);
    const int brow = wn*16 + (l >> 4)*8 + (l & 7);

    for (int p = 0; p < PASSES; ++p){
        float acc[4][2][4];
        #pragma unroll
        for (int ti = 0; ti < 4; ++ti)
            #pragma unroll
            for (int tj = 0; tj < 2; ++tj)
                #pragma unroll
                for (int e = 0; e < 4; ++e) acc[ti][tj][e] = 0.f;

        for (int kc = 0; kc < NCH; ++kc){
            int q = p*NCH + kc;
            if (q + 1 < CHT){ issueB(q + 1, tid, sbase); asm volatile("cp.async.wait_group 1;"); }
            else            { asm volatile("cp.async.wait_group 0;"); }
            __syncthreads();
            uint32_t bufb = sbase + SB + (uint32_t)(q & 1)*32768u;

            #pragma unroll
            for (int ks = 0; ks < 8; ++ks){
                const int acol = kc*KC + ks*16 + (l >> 4)*8;
                const int bcol = ks*16 + ((l >> 3) & 1)*8;
                uint32_t a[4][4], bf[4];
                #pragma unroll
                for (int ti = 0; ti < 4; ++ti)
                    ldsm4(a[ti], sbase + SA + A_off(arow + ti*16, acol));
                ldsm4(bf, bufb + B_off(brow, bcol));
                #pragma unroll
                for (int ti = 0; ti < 4; ++ti)
                    #pragma unroll
                    for (int tj = 0; tj < 2; ++tj)
                        mma16816(acc[ti][tj], a[ti], bf[tj*2], bf[tj*2+1]);
            }
            __syncthreads();
        }
        // ---- pass epilogue: distances -> per-(row-slot) top2 ----
        #pragma unroll
        for (int ti = 0; ti < 4; ++ti)
            #pragma unroll
            for (int tj = 0; tj < 2; ++tj)
                #pragma unroll
                for (int e = 0; e < 4; ++e){
                    int jg = p*PN + wn*16 + tj*8 + (l & 3)*2 + (e & 1);
                    float d = fmaf(-2.f, acc[ti][tj][e], cbn_s[jg]);
                    int r = ti*2 + (e >> 1);
                    if (d < bd[r][0]){
                        bd[r][1] = bd[r][0]; bj[r][1] = bj[r][0];
                        bd[r][0] = d;        bj[r][0] = jg;
                    } else if (d < bd[r][1]){
                        bd[r][1] = d;        bj[r][1] = jg;
                    }
                }
    }

    // ---- dump candidates (overlay B buffers): cand[128][64] of (d, j) ----
    float2* cand = (float2*)(sm + SB);
    #pragma unroll
    for (int r = 0; r < 8; ++r){
        int m = wm*64 + (r >> 1)*16 + (r & 1)*8 + (l >> 2);
        int slot = wn*8 + (l & 3)*2;
        cand[m*64 + slot + 0] = make_float2(bd[r][0], __int_as_float(bj[r][0]));
        cand[m*64 + slot + 1] = make_float2(bd[r][1], __int_as_float(bj[r][1]));
    }
    __syncthreads();

    // ---- per-row: pick candidates, exact fp32 dots (all rows), xnorm, commit contribution ----
    float cm = 0.f;
    if (tid < MT){
        int m = tid;
        float b1 = 3.4e38f; int j1 = 0x7fffffff;
        #pragma unroll 4
        for (int s = 0; s < 64; ++s){
            float2 e = cand[m*64 + s];
            int j = __float_as_int(e.y);
            if (e.x < b1 || (e.x == b1 && j < j1)){ b1 = e.x; j1 = j; }
        }
        int cj[CMAX]; int ncand = 0;
        #pragma unroll 4
        for (int s = 0; s < 64; ++s){
            float2 e = cand[m*64 + s];
            if (e.x <= b1 + MARGIN && ncand < CMAX) cj[ncand++] = __float_as_int(e.y);
        }
        float sacc[CMAX];
        const float* cps[CMAX];
        #pragma unroll
        for (int q2 = 0; q2 < CMAX; ++q2){
            sacc[q2] = 0.f;
            cps[q2] = cb + (size_t)cj[q2 < ncand ? q2 : 0]*CD;
        }
        float xn = 0.f;
        const float* xr = xblk + m;
        #pragma unroll 4
        for (int c = 0; c < CD; ++c){
            float xv = xr[(size_t)c*TD];
            xn = fmaf(xv, xv, xn);
            #pragma unroll
            for (int q2 = 0; q2 < CMAX; ++q2)
                if (q2 < ncand) sacc[q2] = fmaf(xv, cps[q2][c], sacc[q2]);
        }
        float bdx = 3.4e38f; int jf = 0x7fffffff; float dotw = 0.f;
        #pragma unroll
        for (int q2 = 0; q2 < CMAX; ++q2){
            if (q2 < ncand){
                float d = fmaf(-2.f, sacc[q2], cbn_s[cj[q2]]);
                if (d < bdx || (d == bdx && cj[q2] < jf)){ bdx = d; jf = cj[q2]; dotw = sacc[q2]; }
            }
        }
        sidx[m] = jf;
        atomicAdd(&g_counts[jf], 1);
        // commit contribution: ||x||^2 + ||k||^2 - 2 x.k
        cm = fmaf(-2.f, dotw, xn + cbn_s[jf]);
    }
    // block commit reduce over 128 rows (warps 0..3)
    #pragma unroll
    for (int o = 16; o; o >>= 1) cm += __shfl_xor_sync(~0u, cm, o);
    __syncthreads();
    if (tid < MT && (l == 0)) wred[wid] = cm;
    __syncthreads();
    if (tid == 0){
        g_partials[b] = ((wred[0] + wred[1]) + (wred[2] + wred[3]));
    }

    // ---- output: gather q, write out = q (x_st differs from q by < 2e-7) ----
    float* qt = (float*)(sm + SA);              // 128 x 36 floats (A region retired)
    for (int cc = 0; cc < 16; ++cc){            // chunks of 32 c
        __syncthreads();
        #pragma unroll
        for (int it = 0; it < 2; ++it){
            int i = tid + it*NTHR;              // 0..1023 float4s
            int t = i >> 3, c4 = i & 7;
            float4 v = *(const float4*)(cb + (size_t)sidx[t]*CD + cc*32 + c4*4);
            *(float4*)&qt[t*36 + c4*4] = v;
        }
        __syncthreads();
        {
            int t = tid & 127, h = tid >> 7;    // h in 0..3
            #pragma unroll
            for (int cl = 0; cl < 8; ++cl){
                int c = h*8 + cl;
                outblk[(size_t)(cc*32 + c)*TD + t] = qt[t*36 + c];
            }
        }
    }

    // ---- last-CTA finalize ----
    __syncthreads();
    if (tid == 0){
        __threadfence();
        unsigned int old = atomicAdd(&g_done, 1u);
        sflag[0] = (old == (unsigned)(NTILE - 1)) ? 1 : 0;
    }
    __syncthreads();
    if (sflag[0]){
        __threadfence();
        double* sd = (double*)(sm);             // finalize scratch (A/qt retired)
        double s = 0.0;
        for (int i = tid; i < NTILE; i += NTHR) s += (double)g_partials[i];
        sd[tid] = s; __syncthreads();
        for (int o = NTHR/2; o; o >>= 1){ if (tid < o) sd[tid] += sd[tid + o]; __syncthreads(); }
        double commit = sd[0] / ((double)NT * (double)CD);
        __syncthreads();
        double e = 0.0;
        for (int i = tid; i < NB; i += NTHR){
            double p = (double)g_counts[i] / (double)NT;
            e += p * log(p + 1e-7);
        }
        sd[tid] = e; __syncthreads();
        for (int o = NTHR/2; o; o >>= 1){ if (tid < o) sd[tid] += sd[tid + o]; __syncthreads(); }
        if (tid == 0){
            out[(size_t)NN*CD*TD]     = (float)commit;
            out[(size_t)NN*CD*TD + 1] = (float)exp(-sd[0]);
        }
    }
}

extern "C" void kernel_launch(void* const* d_in, const int* in_sizes, int n_in,
                              void* d_out, int out_size){
    const float* x  = (const float*)d_in[0];   // (32, 512, 2048) fp32
    const float* cb = (const float*)d_in[1];   // (1024, 512) fp32
    float* out = (float*)d_out;

    cudaFuncSetAttribute(k_main, cudaFuncAttributeMaxDynamicSharedMemorySize, SMTOT);

    k_norms<<<NB, 128>>>(cb);
    k_main<<<NTILE, NTHR, SMTOT>>>(x, cb, out);
}

// round 10
// speedup vs baseline: 1.0696x; 1.0696x over previous
#include <cuda_runtime.h>
#include <cuda_bf16.h>
#include <cstdint>

#define NB   1024
#define CD   512
#define NN   32
#define TD   2048
#define NT   (NN*TD)      // 65536 rows
#define MT   64           // rows per CTA
#define NTILE (NT/MT)     // 1024 CTAs
#define NTHR 512
#define PASSES 8
#define PN   128          // codes per pass
#define KCH  64           // k per chunk
#define NCHK 8            // chunks per pass
#define CHT  (PASSES*NCHK)// 64 chunks
#define MARGIN 1.5f
#define CMAX 8

typedef unsigned long long ull;

__device__ __align__(16) __nv_bfloat16 g_cb16[NB*CD];
__device__ float g_cbnorm[NB];
__device__ int   g_counts[NB];
__device__ float g_partials[NTILE];
__device__ unsigned int g_done;

// smem map (bytes): A 64x512 bf16 swizzled @0 (65536; later qt / finalize scratch),
// B 2x16384 @65536 (later cand 32KB), cbn @98304, sidx @102400, wred @102656, flag @102720
#define SA    0
#define SB    65536
#define SCBN  98304
#define SIDX  102400
#define SWRED 102656
#define SFLAG 102720
#define SMTOT 102784

static __device__ __forceinline__ uint32_t smem_u32(const void* p){
    uint32_t a; asm("{ .reg .u64 t; cvta.to.shared.u64 t, %1; cvt.u32.u64 %0, t; }" : "=r"(a) : "l"(p));
    return a;
}
// A: 64 rows x 512 cols bf16, 1024B/row, XOR swizzle on 16B chunks
static __device__ __forceinline__ uint32_t A_off(int r, int c){
    int ck = c >> 3;
    int cks = (ck & ~7) | ((ck ^ r) & 7);
    return (uint32_t)(r*1024 + cks*16 + (c&7)*2);
}
// B chunk: 128 codes x 64 k bf16, 128B/row, XOR swizzle
static __device__ __forceinline__ uint32_t B_off(int j, int kk){
    int ck = kk >> 3;
    int cks = (ck ^ j) & 7;
    return (uint32_t)(j*128 + cks*16 + (kk&7)*2);
}
static __device__ __forceinline__ void ldsm4(uint32_t* r, uint32_t addr){
    asm volatile("ldmatrix.sync.aligned.m8n8.x4.shared.b16 {%0,%1,%2,%3}, [%4];"
        : "=r"(r[0]), "=r"(r[1]), "=r"(r[2]), "=r"(r[3]) : "r"(addr));
}
static __device__ __forceinline__ void mma16816(float* c, const uint32_t* a, uint32_t b0, uint32_t b1){
    asm volatile("mma.sync.aligned.m16n8k16.row.col.f32.bf16.bf16.f32 "
        "{%0,%1,%2,%3}, {%4,%5,%6,%7}, {%8,%9}, {%0,%1,%2,%3};"
        : "+f"(c[0]), "+f"(c[1]), "+f"(c[2]), "+f"(c[3])
        : "r"(a[0]), "r"(a[1]), "r"(a[2]), "r"(a[3]), "r"(b0), "r"(b1));
}

// ---------------- kernel 0: codebook norms + bf16 convert + zero counts/ticket ----------------
__global__ void k_norms(const float* __restrict__ cb){
    int j = blockIdx.x;
    float s = 0.f;
    for (int c = threadIdx.x; c < CD; c += 128){
        float v = cb[(size_t)j*CD + c];
        g_cb16[(size_t)j*CD + c] = __float2bfloat16(v);
        s = fmaf(v, v, s);
    }
    #pragma unroll
    for (int o = 16; o; o >>= 1) s += __shfl_xor_sync(~0u, s, o);
    __shared__ float ws[4];
    if ((threadIdx.x & 31) == 0) ws[threadIdx.x >> 5] = s;
    __syncthreads();
    if (threadIdx.x == 0){
        g_cbnorm[j] = (ws[0] + ws[1]) + (ws[2] + ws[3]);
        g_counts[j] = 0;
        if (j == 0) g_done = 0u;
    }
}

// ---------------- B chunk stage via cp.async ----------------
static __device__ __forceinline__ void issueB(int q, int tid, uint32_t sbase){
    int p = q >> 3, kc = q & 7;
    const __nv_bfloat16* src0 = g_cb16 + (size_t)p*PN*CD + kc*KCH;
    uint32_t bufb = sbase + SB + (uint32_t)(q & 1)*16384u;
    #pragma unroll
    for (int it = 0; it < 2; ++it){
        int idx = tid + it*NTHR;              // 0..1023 16B units
        int j = idx >> 3, ck = idx & 7;
        uint32_t dst = bufb + (uint32_t)(j*128 + (((ck ^ j) & 7) << 4));
        const void* srcp = (const void*)(src0 + (size_t)j*CD + ck*8);
        asm volatile("cp.async.cg.shared.global [%0], [%1], 16;" :: "r"(dst), "l"(srcp));
    }
    asm volatile("cp.async.commit_group;");
}

// ---------------- kernel 1: fused GEMM + top2 + refine + output + commit + finalize ----------------
__global__ __launch_bounds__(NTHR, 2)
void k_main(const float* __restrict__ x, const float* __restrict__ cb, float* __restrict__ out){
    extern __shared__ char sm[];
    const uint32_t sbase = smem_u32(sm);
    const int tid = threadIdx.x;
    const int wid = tid >> 5, l = tid & 31;
    const int wm = wid >> 3, wn = wid & 7;        // 2 M-warps x 8 N-warps
    const int b = blockIdx.x, n = b >> 5, t0 = (b & 31) * MT;
    const float* xblk = x + (size_t)n*CD*TD + t0;
    float* outblk     = out + (size_t)n*CD*TD + t0;
    float* cbn_s = (float*)(sm + SCBN);
    int*   sidx  = (int*)(sm + SIDX);
    float* wred  = (float*)(sm + SWRED);
    int*   sflag = (int*)(sm + SFLAG);

    for (int i = tid; i < NB; i += NTHR) cbn_s[i] = g_cbnorm[i];

    // ---- stage A: x tile -> bf16, swizzled [t][c] ----
    #pragma unroll 4
    for (int it = 0; it < 32; ++it){
        int idx = tid + it*NTHR;
        int t = idx & 63, c = (idx >> 6) * 2;
        float v0 = xblk[(size_t)c*TD + t];
        float v1 = xblk[(size_t)(c+1)*TD + t];
        __nv_bfloat162 pk = __floats2bfloat162_rn(v0, v1);
        *(__nv_bfloat162*)(sm + SA + A_off(t, c)) = pk;
    }
    __syncthreads();

    issueB(0, tid, sbase);

    float bd[4][2]; int bj[4][2];
    #pragma unroll
    for (int r = 0; r < 4; ++r){
        bd[r][0] = bd[r][1] = 3.4e38f; bj[r][0] = bj[r][1] = 0;
    }

    const int arow = wm*32 + ((l >> 3) & 1)*8 + (l & 7);
    const int brow = wn*16 + (l >> 4)*8 + (l & 7);

    for (int p = 0; p < PASSES; ++p){
        float acc[2][2][4];
        #pragma unroll
        for (int ti = 0; ti < 2; ++ti)
            #pragma unroll
            for (int tj = 0; tj < 2; ++tj)
                #pragma unroll
                for (int e = 0; e < 4; ++e) acc[ti][tj][e] = 0.f;

        for (int kc = 0; kc < NCHK; ++kc){
            int q = p*NCHK + kc;
            if (q + 1 < CHT){ issueB(q + 1, tid, sbase); asm volatile("cp.async.wait_group 1;"); }
            else            { asm volatile("cp.async.wait_group 0;"); }
            __syncthreads();
            uint32_t bufb = sbase + SB + (uint32_t)(q & 1)*16384u;

            #pragma unroll
            for (int ks = 0; ks < 4; ++ks){
                const int acol = kc*KCH + ks*16 + (l >> 4)*8;
                const int bcol = ks*16 + ((l >> 3) & 1)*8;
                uint32_t a[2][4], bf[4];
                #pragma unroll
                for (int ti = 0; ti < 2; ++ti)
                    ldsm4(a[ti], sbase + SA + A_off(arow + ti*16, acol));
                ldsm4(bf, bufb + B_off(brow, bcol));
                #pragma unroll
                for (int ti = 0; ti < 2; ++ti)
                    #pragma unroll
                    for (int tj = 0; tj < 2; ++tj)
                        mma16816(acc[ti][tj], a[ti], bf[tj*2], bf[tj*2+1]);
            }
            __syncthreads();
        }
        // ---- pass epilogue: distances -> per-(row-slot) top2 ----
        #pragma unroll
        for (int ti = 0; ti < 2; ++ti)
            #pragma unroll
            for (int tj = 0; tj < 2; ++tj)
                #pragma unroll
                for (int e = 0; e < 4; ++e){
                    int jg = p*PN + wn*16 + tj*8 + (l & 3)*2 + (e & 1);
                    float d = fmaf(-2.f, acc[ti][tj][e], cbn_s[jg]);
                    int r = ti*2 + (e >> 1);
                    if (d < bd[r][0]){
                        bd[r][1] = bd[r][0]; bj[r][1] = bj[r][0];
                        bd[r][0] = d;        bj[r][0] = jg;
                    } else if (d < bd[r][1]){
                        bd[r][1] = d;        bj[r][1] = jg;
                    }
                }
    }

    // ---- dump candidates (overlay B buffers): cand[64][64] of (d, j) ----
    float2* cand = (float2*)(sm + SB);
    #pragma unroll
    for (int r = 0; r < 4; ++r){
        int m = wm*32 + (r >> 1)*16 + (r & 1)*8 + (l >> 2);
        int slot = wn*8 + (l & 3)*2;
        cand[m*64 + slot + 0] = make_float2(bd[r][0], __int_as_float(bj[r][0]));
        cand[m*64 + slot + 1] = make_float2(bd[r][1], __int_as_float(bj[r][1]));
    }
    __syncthreads();

    // ---- per-row pick + exact fp32 refine if margin small ----
    if (tid < MT){
        int m = tid;
        float b1 = 3.4e38f; int j1 = 0x7fffffff;
        #pragma unroll 4
        for (int s = 0; s < 64; ++s){
            float2 e = cand[m*64 + s];
            int j = __float_as_int(e.y);
            if (e.x < b1 || (e.x == b1 && j < j1)){ b1 = e.x; j1 = j; }
        }
        int cj[CMAX]; int ncand = 0;
        #pragma unroll 4
        for (int s = 0; s < 64; ++s){
            float2 e = cand[m*64 + s];
            if (e.x <= b1 + MARGIN && ncand < CMAX) cj[ncand++] = __float_as_int(e.y);
        }
        int jf = j1;
        if (ncand > 1){
            float sacc[CMAX];
            const float* cps[CMAX];
            #pragma unroll
            for (int q2 = 0; q2 < CMAX; ++q2){
                sacc[q2] = 0.f;
                cps[q2] = cb + (size_t)cj[q2 < ncand ? q2 : 0]*CD;
            }
            const float* xr = xblk + m;
            #pragma unroll 4
            for (int c = 0; c < CD; ++c){
                float xv = xr[(size_t)c*TD];
                #pragma unroll
                for (int q2 = 0; q2 < CMAX; ++q2)
                    if (q2 < ncand) sacc[q2] = fmaf(xv, cps[q2][c], sacc[q2]);
            }
            float bdx = 3.4e38f; jf = 0x7fffffff;
            #pragma unroll
            for (int q2 = 0; q2 < CMAX; ++q2){
                if (q2 < ncand){
                    float d = fmaf(-2.f, sacc[q2], cbn_s[cj[q2]]);
                    if (d < bdx || (d == bdx && cj[q2] < jf)){ bdx = d; jf = cj[q2]; }
                }
            }
        }
        sidx[m] = jf;
        atomicAdd(&g_counts[jf], 1);
    }
    __syncthreads();

    // ---- output: gather q, write out = q, commit via coalesced x read ----
    float* qt = (float*)(sm + SA);              // 64 x 36 floats (A region retired)
    float csum = 0.f;
    for (int cc = 0; cc < 16; ++cc){            // chunks of 32 c
        __syncthreads();
        {
            int i = tid;                        // 0..511 float4s (64 rows x 8)
            int t = i >> 3, c4 = i & 7;
            float4 v = *(const float4*)(cb + (size_t)sidx[t]*CD + cc*32 + c4*4);
            *(float4*)&qt[t*36 + c4*4] = v;
        }
        __syncthreads();
        {
            int t = tid & 63, h = tid >> 6;     // h in 0..7
            #pragma unroll
            for (int cl = 0; cl < 4; ++cl){
                int c = h*4 + cl;
                float q  = qt[t*36 + c];
                float xv = xblk[(size_t)(cc*32 + c)*TD + t];
                outblk[(size_t)(cc*32 + c)*TD + t] = q;
                float df = __fsub_rn(xv, q);
                csum = fmaf(df, df, csum);
            }
        }
    }
    #pragma unroll
    for (int o = 16; o; o >>= 1) csum += __shfl_xor_sync(~0u, csum, o);
    __syncthreads();
    if ((tid & 31) == 0) wred[wid] = csum;
    __syncthreads();
    if (tid == 0){
        float s = 0.f;
        #pragma unroll
        for (int w = 0; w < 16; ++w) s += wred[w];
        g_partials[b] = s;
    }

    // ---- last-CTA finalize ----
    __syncthreads();
    if (tid == 0){
        __threadfence();
        unsigned int old = atomicAdd(&g_done, 1u);
        sflag[0] = (old == (unsigned)(NTILE - 1)) ? 1 : 0;
    }
    __syncthreads();
    if (sflag[0]){
        __threadfence();
        double* sd = (double*)(sm);             // finalize scratch (A/qt retired)
        double s = 0.0;
        for (int i = tid; i < NTILE; i += NTHR) s += (double)g_partials[i];
        sd[tid] = s; __syncthreads();
        for (int o = NTHR/2; o; o >>= 1){ if (tid < o) sd[tid] += sd[tid + o]; __syncthreads(); }
        double commit = sd[0] / ((double)NT * (double)CD);
        __syncthreads();
        double e = 0.0;
        for (int i = tid; i < NB; i += NTHR){
            double p = (double)g_counts[i] / (double)NT;
            e += p * log(p + 1e-7);
        }
        sd[tid] = e; __syncthreads();
        for (int o = NTHR/2; o; o >>= 1){ if (tid < o) sd[tid] += sd[tid + o]; __syncthreads(); }
        if (tid == 0){
            out[(size_t)NN*CD*TD]     = (float)commit;
            out[(size_t)NN*CD*TD + 1] = (float)exp(-sd[0]);
        }
    }
}

extern "C" void kernel_launch(void* const* d_in, const int* in_sizes, int n_in,
                              void* d_out, int out_size){
    const float* x  = (const float*)d_in[0];   // (32, 512, 2048) fp32
    const float* cb = (const float*)d_in[1];   // (1024, 512) fp32
    float* out = (float*)d_out;

    cudaFuncSetAttribute(k_main, cudaFuncAttributeMaxDynamicSharedMemorySize, SMTOT);

    k_norms<<<NB, 128>>>(cb);
    k_main<<<NTILE, NTHR, SMTOT>>>(x, cb, out);
}